// round 14
// baseline (speedup 1.0000x reference)
#include <cuda_runtime.h>
#include <cuda_fp16.h>
#include <math.h>
#include <stdint.h>

#define TOKENS 65536
#define DDIM   512
#define NEXP   8
#define HDIM   2048
#define CAP    65536
#define MTILES 1032   // ceil((131072 + 8*127)/128)

// ---------------- device scratch (no allocs allowed) -------------------------
__device__ int   g_counts [NEXP];
__device__ int   g_tokens [NEXP * CAP];   // token*2 + slot
__device__ float g_gates  [NEXP * CAP];
__device__ __half g_xh [(size_t)TOKENS * DDIM];          // x fp16 (written by router)
__device__ __half g_w1t[(size_t)NEXP * HDIM * DDIM];     // [E][H][D] K-major
__device__ __half g_w2t[(size_t)NEXP * DDIM * HDIM];     // [E][D][H] K-major
__device__ __half g_h[(size_t)(2 * TOKENS + 1024) * HDIM];  // aligned compact hidden

// ---------------- helpers -----------------------------------------------------
__device__ __forceinline__ uint32_t smem_u32(const void* p) {
    uint32_t a;
    asm("{ .reg .u64 t; cvta.to.shared.u64 t, %1; cvt.u32.u64 %0, t; }" : "=r"(a) : "l"(p));
    return a;
}
__device__ __forceinline__ void ldsm4(uint32_t* r, uint32_t addr) {
    asm volatile("ldmatrix.sync.aligned.m8n8.x4.shared.b16 {%0,%1,%2,%3}, [%4];"
        : "=r"(r[0]), "=r"(r[1]), "=r"(r[2]), "=r"(r[3]) : "r"(addr));
}
__device__ __forceinline__ void mma16816(float* c, const uint32_t* a, const uint32_t* b) {
    asm volatile(
        "mma.sync.aligned.m16n8k16.row.col.f32.f16.f16.f32 "
        "{%0,%1,%2,%3}, {%4,%5,%6,%7}, {%8,%9}, {%0,%1,%2,%3};"
        : "+f"(c[0]), "+f"(c[1]), "+f"(c[2]), "+f"(c[3])
        : "r"(a[0]), "r"(a[1]), "r"(a[2]), "r"(a[3]), "r"(b[0]), "r"(b[1]));
}
#define CPA(dst, src) \
    asm volatile("cp.async.cg.shared.global [%0], [%1], 16;" :: "r"(dst), "l"(src) : "memory")
#define CPC()  asm volatile("cp.async.commit_group;" ::: "memory")
#define CPW2() asm volatile("cp.async.wait_group 2;" ::: "memory")
#define REDADD(p, v) \
    asm volatile("red.global.add.f32 [%0], %1;" :: "l"(p), "f"(v) : "memory")

__device__ __forceinline__ uint32_t hpack2(__half a, __half b) {
    union { __half h[2]; uint32_t u; } t;
    t.h[0] = a; t.h[1] = b;
    return t.u;
}

// ---------------- prep kernels ------------------------------------------------
__global__ void zero_counts_kernel() { if (threadIdx.x < NEXP) g_counts[threadIdx.x] = 0; }

// transpose [R][C] fp32 -> [C][R] fp16 (per expert)
template<int SEL>   // 0: w1 (R=512,C=2048), 1: w2 (R=2048,C=512)
__global__ void t_w_kernel(const float* __restrict__ src) {
    constexpr int R = SEL ? HDIM : DDIM;
    constexpr int C = SEL ? DDIM : HDIM;
    __half* dst = SEL ? g_w2t : g_w1t;
    __shared__ float t[32][33];
    int e = blockIdx.z;
    const float* s = src + (size_t)e * R * C;
    int c0 = blockIdx.x * 32, r0 = blockIdx.y * 32;
    int tx = threadIdx.x, ty = threadIdx.y;
    #pragma unroll
    for (int j = 0; j < 4; j++)
        t[ty + j * 8][tx] = s[(size_t)(r0 + ty + j * 8) * C + c0 + tx];
    __syncthreads();
    #pragma unroll
    for (int j = 0; j < 4; j++) {
        float v = t[tx][ty + j * 8];
        size_t o = ((size_t)e * C + c0 + ty + j * 8) * R + r0 + tx;
        dst[o] = __float2half_rn(v);
    }
}

// ---------------- router (+ fused x -> fp16 conversion) -----------------------
__global__ void router_kernel(const float* __restrict__ x,
                              const float* __restrict__ rw,
                              const float* __restrict__ rb) {
    __shared__ float srw[DDIM * NEXP];
    int tid = threadIdx.x;
    for (int i = tid; i < DDIM * NEXP; i += blockDim.x) srw[i] = rw[i];
    __syncthreads();
    int warp = tid >> 5, lane = tid & 31;
    int t = blockIdx.x * 8 + warp;
    const float* xr = x + (size_t)t * DDIM;

    float acc[NEXP];
    #pragma unroll
    for (int e = 0; e < NEXP; e++) acc[e] = 0.f;
    for (int d = lane; d < DDIM; d += 32) {
        float xv = xr[d];
        #pragma unroll
        for (int e = 0; e < NEXP; e++) acc[e] += xv * srw[d * NEXP + e];
    }
    #pragma unroll
    for (int e = 0; e < NEXP; e++) {
        #pragma unroll
        for (int o = 16; o > 0; o >>= 1)
            acc[e] += __shfl_xor_sync(0xffffffffu, acc[e], o);
    }

    // fused: convert this token's row to fp16
    const float4* xr4 = (const float4*)xr;
    #pragma unroll
    for (int it = 0; it < 4; it++) {
        float4 v = xr4[lane + it * 32];
        uint2 H;
        H.x = hpack2(__float2half_rn(v.x), __float2half_rn(v.y));
        H.y = hpack2(__float2half_rn(v.z), __float2half_rn(v.w));
        *(uint2*)(g_xh + (size_t)t * DDIM + (lane + it * 32) * 4) = H;
    }

    if (lane == 0) {
        float l[NEXP];
        #pragma unroll
        for (int e = 0; e < NEXP; e++) l[e] = acc[e] + rb[e];
        int e1 = 0;
        #pragma unroll
        for (int e = 1; e < NEXP; e++) if (l[e] > l[e1]) e1 = e;
        int e2 = (e1 == 0) ? 1 : 0;
        #pragma unroll
        for (int e = 0; e < NEXP; e++)
            if (e != e1 && l[e] > l[e2]) e2 = e;
        float d2 = expf(l[e2] - l[e1]);
        float g2 = d2 / (1.f + d2);
        float g1 = 1.f - g2;
        int p1 = atomicAdd(&g_counts[e1], 1);
        g_tokens[e1 * CAP + p1] = t * 2 + 0;  g_gates[e1 * CAP + p1] = g1;
        int p2 = atomicAdd(&g_counts[e2], 1);
        g_tokens[e2 * CAP + p2] = t * 2 + 1;  g_gates[e2 * CAP + p2] = g2;
    }
}

// ---------------- HMMA GEMM (128x128, 256 thr, NSTG=4, 2 CTA/SM) --------------
// M-grid covers the 128-aligned compact row space of ALL experts: zero no-ops.
// G2 epilogue: fire-and-forget red.global.add.f32 into out (out pre-zeroed);
// each out element receives exactly two commutative fp32 adds -> deterministic.
#define STG   20480
#define NSTG  4
#define DSMEM (NSTG * STG)

template<bool G1>
__global__ void __launch_bounds__(256, 2)
hgemm_kernel(const float* __restrict__ bias_vec, float* __restrict__ out) {
    constexpr int KTOT = G1 ? DDIM : HDIM;
    constexpr int NTOT = G1 ? HDIM : DDIM;
    constexpr int NC   = KTOT / 32;

    // ---- locate expert from aligned-compact tile index ----
    int m0g = blockIdx.y * 128;
    int e = -1, abase = 0, cnt = 0;
    #pragma unroll
    for (int k = 0; k < NEXP; k++) {
        if (e < 0) {
            int ck = g_counts[k];
            int ak = (ck + 127) & ~127;
            if (m0g < abase + ak) { e = k; cnt = ck; }
            else abase += ak;
        }
    }
    if (e < 0) return;                  // beyond total aligned rows
    int m0 = m0g - abase;               // local tile start, always < cnt
    int n0 = blockIdx.x * 128;

    extern __shared__ char dsm[];
    __shared__ int   s_tok[128];
    __shared__ float s_gate[128];
    __shared__ float s_bias[128];

    int tid = threadIdx.x;
    int lane = tid & 31, wid = tid >> 5;

    if (tid < 128) {
        int m = m0 + tid; if (m > cnt - 1) m = cnt - 1;
        s_tok[tid]  = g_tokens[e * CAP + m];
        s_gate[tid] = g_gates [e * CAP + m];
        s_bias[tid] = bias_vec[(size_t)e * NTOT + n0 + tid];
    }
    __syncthreads();

    // ---- cp.async mapping: thread t -> row t/2, 32B half (t&1) of 64B row ----
    int r    = tid >> 1;
    int eoff = (tid & 1) * 16;
    size_t aRow;
    if (G1) aRow = (size_t)(s_tok[r] >> 1) * DDIM;
    else {
        int mm = m0 + r; if (mm > cnt - 1) mm = cnt - 1;
        aRow = (size_t)(abase + mm) * HDIM;
    }
    const __half* aP = (G1 ? g_xh : g_h) + aRow + eoff;
    const __half* bP = (G1 ? g_w1t : g_w2t) +
                       ((size_t)e * NTOT + n0 + r) * KTOT + eoff;

    uint32_t sb = smem_u32(dsm);
    uint32_t dA = sb + 80 * r + 32 * (tid & 1);
    uint32_t dB = dA + 10240;

    // ---- ldmatrix base addresses ----
    int wm = wid & 3, wn = wid >> 2;       // warp tile: rows wm*32, cols wn*64
    uint32_t aOff = sb + 80 * (wm * 32 + (lane & 15)) + 16 * (lane >> 4);
    uint32_t bOff = sb + 10240 +
                    80 * (wn * 64 + (lane & 7) + 8 * (lane >> 4)) +
                    16 * ((lane >> 3) & 1);

    float c[2][8][4];
    #pragma unroll
    for (int i = 0; i < 2; i++)
        #pragma unroll
        for (int j = 0; j < 8; j++)
            #pragma unroll
            for (int q = 0; q < 4; q++) c[i][j][q] = 0.f;

    // ---- prologue: stages 0,1,2 ----
    #pragma unroll
    for (int i = 0; i < 3; i++) {
        uint32_t st = i * STG;
        int k0 = i * 32;
        CPA(dA + st, aP + k0);  CPA(dA + st + 16, aP + k0 + 8);
        CPA(dB + st, bP + k0);  CPA(dB + st + 16, bP + k0 + 8);
        CPC();
    }

    for (int i = 0; i < NC; i++) {
        CPW2();
        __syncthreads();
        if (i + 3 < NC) {
            uint32_t st = ((i + 3) % NSTG) * STG;
            int k0 = (i + 3) * 32;
            CPA(dA + st, aP + k0);  CPA(dA + st + 16, aP + k0 + 8);
            CPA(dB + st, bP + k0);  CPA(dB + st + 16, bP + k0 + 8);
        }
        CPC();

        uint32_t st = (i % NSTG) * STG;
        #pragma unroll
        for (int kk = 0; kk < 2; kk++) {
            uint32_t a0[4], a1[4];
            ldsm4(a0, aOff + st + kk * 32);
            ldsm4(a1, aOff + st + kk * 32 + 1280);
            #pragma unroll
            for (int ng = 0; ng < 4; ng++) {
                uint32_t bf[4];
                ldsm4(bf, bOff + st + ng * 1280 + kk * 32);
                mma16816(c[0][2 * ng],     a0, bf);
                mma16816(c[0][2 * ng + 1], a0, bf + 2);
                mma16816(c[1][2 * ng],     a1, bf);
                mma16816(c[1][2 * ng + 1], a1, bf + 2);
            }
        }
    }

    // ---- epilogue: stage C in smem (pitch 132 floats), then coalesced out ----
    __syncthreads();
    float* sC = (float*)dsm;
    #pragma unroll
    for (int mi = 0; mi < 2; mi++) {
        #pragma unroll
        for (int nf = 0; nf < 8; nf++) {
            int rm = wm * 32 + mi * 16 + (lane >> 2);
            int cn = wn * 64 + nf * 8 + 2 * (lane & 3);
            *(float2*)&sC[rm * 132 + cn]       = make_float2(c[mi][nf][0], c[mi][nf][1]);
            *(float2*)&sC[(rm + 8) * 132 + cn] = make_float2(c[mi][nf][2], c[mi][nf][3]);
        }
    }
    __syncthreads();

    int rr = tid >> 1;
    int cb = (tid & 1) * 64;
    bool mv = (m0 + rr) < cnt;
    if (G1) {
        if (mv) {
            size_t rowb = (size_t)(abase + m0 + rr) * HDIM + n0 + cb;
            #pragma unroll
            for (int g = 0; g < 8; g++) {
                uint32_t H[4];
                #pragma unroll
                for (int p = 0; p < 4; p++) {
                    int col = cb + g * 8 + 2 * p;
                    float v0 = fmaxf(sC[rr * 132 + col]     + s_bias[col],     0.f);
                    float v1 = fmaxf(sC[rr * 132 + col + 1] + s_bias[col + 1], 0.f);
                    H[p] = hpack2(__float2half_rn(v0), __float2half_rn(v1));
                }
                *(uint4*)(g_h + rowb + g * 8) = *(uint4*)H;
            }
        }
    } else {
        if (mv) {
            int tok  = s_tok[rr] >> 1;
            float gt = s_gate[rr];
            float* dst = out + (size_t)tok * DDIM + n0 + cb;
            #pragma unroll
            for (int g = 0; g < 16; g++) {
                int col = cb + g * 4;
                REDADD(dst + g * 4 + 0, gt * (sC[rr * 132 + col]     + s_bias[col]));
                REDADD(dst + g * 4 + 1, gt * (sC[rr * 132 + col + 1] + s_bias[col + 1]));
                REDADD(dst + g * 4 + 2, gt * (sC[rr * 132 + col + 2] + s_bias[col + 2]));
                REDADD(dst + g * 4 + 3, gt * (sC[rr * 132 + col + 3] + s_bias[col + 3]));
            }
        }
    }
}

// ---------------- launch ------------------------------------------------------
extern "C" void kernel_launch(void* const* d_in, const int* in_sizes, int n_in,
                              void* d_out, int out_size) {
    const float* x   = (const float*)d_in[0];
    const float* rw  = (const float*)d_in[1];
    const float* rb  = (const float*)d_in[2];
    const float* w1  = (const float*)d_in[3];
    const float* b1  = (const float*)d_in[4];
    const float* w2  = (const float*)d_in[5];
    const float* b2  = (const float*)d_in[6];
    float*       out = (float*)d_out;

    cudaFuncSetAttribute(hgemm_kernel<true>,
                         cudaFuncAttributeMaxDynamicSharedMemorySize, DSMEM);
    cudaFuncSetAttribute(hgemm_kernel<false>,
                         cudaFuncAttributeMaxDynamicSharedMemorySize, DSMEM);

    cudaMemsetAsync(out, 0, (size_t)out_size * sizeof(float));

    // launch order keeps hgemm1 in the ncu-profiled slot (#4 kernel)
    zero_counts_kernel<<<1, 32>>>();
    router_kernel<<<TOKENS / 8, 256>>>(x, rw, rb);
    t_w_kernel<0><<<dim3(HDIM / 32, DDIM / 32, NEXP), dim3(32, 8)>>>(w1);
    hgemm_kernel<true ><<<dim3(HDIM / 128, MTILES), 256, DSMEM>>>(b1, nullptr);
    t_w_kernel<1><<<dim3(DDIM / 32, HDIM / 32, NEXP), dim3(32, 8)>>>(w2);
    hgemm_kernel<false><<<dim3(DDIM / 128, MTILES), 256, DSMEM>>>(b2, out);
}

// round 15
// speedup vs baseline: 1.0393x; 1.0393x over previous
#include <cuda_runtime.h>
#include <cuda_fp16.h>
#include <math.h>
#include <stdint.h>

#define TOKENS 65536
#define DDIM   512
#define NEXP   8
#define HDIM   2048
#define CAP    65536
#define MTILES 1032   // ceil((131072 + 8*127)/128)

// ---------------- device scratch (no allocs allowed) -------------------------
__device__ int   g_counts [NEXP];
__device__ int   g_tokens [NEXP * CAP];   // token*2 + slot
__device__ float g_gates  [NEXP * CAP];
__device__ __half g_xh [(size_t)TOKENS * DDIM];          // x fp16 (written by router)
__device__ __half g_w1t[(size_t)NEXP * HDIM * DDIM];     // [E][H][D] K-major
__device__ __half g_w2t[(size_t)NEXP * DDIM * HDIM];     // [E][D][H] K-major
__device__ __half g_h[(size_t)(2 * TOKENS + 1024) * HDIM];  // aligned compact hidden
__device__ __half g_y[(size_t)2 * TOKENS * DDIM];        // slot outputs (fp16)

// ---------------- helpers -----------------------------------------------------
__device__ __forceinline__ uint32_t smem_u32(const void* p) {
    uint32_t a;
    asm("{ .reg .u64 t; cvta.to.shared.u64 t, %1; cvt.u32.u64 %0, t; }" : "=r"(a) : "l"(p));
    return a;
}
__device__ __forceinline__ void ldsm4(uint32_t* r, uint32_t addr) {
    asm volatile("ldmatrix.sync.aligned.m8n8.x4.shared.b16 {%0,%1,%2,%3}, [%4];"
        : "=r"(r[0]), "=r"(r[1]), "=r"(r[2]), "=r"(r[3]) : "r"(addr));
}
__device__ __forceinline__ void mma16816(float* c, const uint32_t* a, const uint32_t* b) {
    asm volatile(
        "mma.sync.aligned.m16n8k16.row.col.f32.f16.f16.f32 "
        "{%0,%1,%2,%3}, {%4,%5,%6,%7}, {%8,%9}, {%0,%1,%2,%3};"
        : "+f"(c[0]), "+f"(c[1]), "+f"(c[2]), "+f"(c[3])
        : "r"(a[0]), "r"(a[1]), "r"(a[2]), "r"(a[3]), "r"(b[0]), "r"(b[1]));
}
#define CPA(dst, src) \
    asm volatile("cp.async.cg.shared.global [%0], [%1], 16;" :: "r"(dst), "l"(src) : "memory")
#define CPC()  asm volatile("cp.async.commit_group;" ::: "memory")
#define CPW2() asm volatile("cp.async.wait_group 2;" ::: "memory")

__device__ __forceinline__ uint32_t hpack2(__half a, __half b) {
    union { __half h[2]; uint32_t u; } t;
    t.h[0] = a; t.h[1] = b;
    return t.u;
}

// ---------------- prep kernels ------------------------------------------------
__global__ void zero_counts_kernel() { if (threadIdx.x < NEXP) g_counts[threadIdx.x] = 0; }

// transpose [R][C] fp32 -> [C][R] fp16 (per expert)
template<int SEL>   // 0: w1 (R=512,C=2048), 1: w2 (R=2048,C=512)
__global__ void t_w_kernel(const float* __restrict__ src) {
    constexpr int R = SEL ? HDIM : DDIM;
    constexpr int C = SEL ? DDIM : HDIM;
    __half* dst = SEL ? g_w2t : g_w1t;
    __shared__ float t[32][33];
    int e = blockIdx.z;
    const float* s = src + (size_t)e * R * C;
    int c0 = blockIdx.x * 32, r0 = blockIdx.y * 32;
    int tx = threadIdx.x, ty = threadIdx.y;
    #pragma unroll
    for (int j = 0; j < 4; j++)
        t[ty + j * 8][tx] = s[(size_t)(r0 + ty + j * 8) * C + c0 + tx];
    __syncthreads();
    #pragma unroll
    for (int j = 0; j < 4; j++) {
        float v = t[tx][ty + j * 8];
        size_t o = ((size_t)e * C + c0 + ty + j * 8) * R + r0 + tx;
        dst[o] = __float2half_rn(v);
    }
}

// ---------------- router (single x pass: logits + fp16 convert) ---------------
__global__ void router_kernel(const float* __restrict__ x,
                              const float* __restrict__ rw,
                              const float* __restrict__ rb) {
    __shared__ float srw[DDIM * NEXP];
    int tid = threadIdx.x;
    for (int i = tid; i < DDIM * NEXP; i += blockDim.x) srw[i] = rw[i];
    __syncthreads();
    int warp = tid >> 5, lane = tid & 31;
    int t = blockIdx.x * 8 + warp;
    const float4* xr4 = (const float4*)(x + (size_t)t * DDIM);

    float acc[NEXP];
    #pragma unroll
    for (int e = 0; e < NEXP; e++) acc[e] = 0.f;

    #pragma unroll
    for (int it = 0; it < 4; it++) {
        float4 v = xr4[lane + it * 32];
        int d0 = (lane + it * 32) * 4;
        float vv[4] = {v.x, v.y, v.z, v.w};
        #pragma unroll
        for (int j = 0; j < 4; j++) {
            #pragma unroll
            for (int e = 0; e < NEXP; e++)
                acc[e] += vv[j] * srw[(d0 + j) * NEXP + e];
        }
        uint2 H;
        H.x = hpack2(__float2half_rn(v.x), __float2half_rn(v.y));
        H.y = hpack2(__float2half_rn(v.z), __float2half_rn(v.w));
        *(uint2*)(g_xh + (size_t)t * DDIM + (size_t)(lane + it * 32) * 4) = H;
    }
    #pragma unroll
    for (int e = 0; e < NEXP; e++) {
        #pragma unroll
        for (int o = 16; o > 0; o >>= 1)
            acc[e] += __shfl_xor_sync(0xffffffffu, acc[e], o);
    }

    if (lane == 0) {
        float l[NEXP];
        #pragma unroll
        for (int e = 0; e < NEXP; e++) l[e] = acc[e] + rb[e];
        int e1 = 0;
        #pragma unroll
        for (int e = 1; e < NEXP; e++) if (l[e] > l[e1]) e1 = e;
        int e2 = (e1 == 0) ? 1 : 0;
        #pragma unroll
        for (int e = 0; e < NEXP; e++)
            if (e != e1 && l[e] > l[e2]) e2 = e;
        float d2 = expf(l[e2] - l[e1]);
        float g2 = d2 / (1.f + d2);
        float g1 = 1.f - g2;
        int p1 = atomicAdd(&g_counts[e1], 1);
        g_tokens[e1 * CAP + p1] = t * 2 + 0;  g_gates[e1 * CAP + p1] = g1;
        int p2 = atomicAdd(&g_counts[e2], 1);
        g_tokens[e2 * CAP + p2] = t * 2 + 1;  g_gates[e2 * CAP + p2] = g2;
    }
}

// ---------------- HMMA GEMM (128x128, 256 thr, NSTG=4, 2 CTA/SM) --------------
// M-grid covers the 128-aligned compact row space of ALL experts: zero no-ops.
#define STG   20480
#define NSTG  4
#define DSMEM (NSTG * STG)

template<bool G1>
__global__ void __launch_bounds__(256, 2)
hgemm_kernel(const float* __restrict__ bias_vec) {
    constexpr int KTOT = G1 ? DDIM : HDIM;
    constexpr int NTOT = G1 ? HDIM : DDIM;
    constexpr int NC   = KTOT / 32;

    // ---- locate expert from aligned-compact tile index ----
    int m0g = blockIdx.y * 128;
    int e = -1, abase = 0, cnt = 0;
    #pragma unroll
    for (int k = 0; k < NEXP; k++) {
        if (e < 0) {
            int ck = g_counts[k];
            int ak = (ck + 127) & ~127;
            if (m0g < abase + ak) { e = k; cnt = ck; }
            else abase += ak;
        }
    }
    if (e < 0) return;                  // beyond total aligned rows
    int m0 = m0g - abase;               // local tile start, always < cnt
    int n0 = blockIdx.x * 128;

    extern __shared__ char dsm[];
    __shared__ int   s_tok[128];
    __shared__ float s_gate[128];
    __shared__ float s_bias[128];

    int tid = threadIdx.x;
    int lane = tid & 31, wid = tid >> 5;

    if (tid < 128) {
        int m = m0 + tid; if (m > cnt - 1) m = cnt - 1;
        s_tok[tid]  = g_tokens[e * CAP + m];
        s_gate[tid] = g_gates [e * CAP + m];
        s_bias[tid] = bias_vec[(size_t)e * NTOT + n0 + tid];
    }
    __syncthreads();

    // ---- cp.async mapping: thread t -> row t/2, 32B half (t&1) of 64B row ----
    int r    = tid >> 1;
    int eoff = (tid & 1) * 16;
    size_t aRow;
    if (G1) aRow = (size_t)(s_tok[r] >> 1) * DDIM;
    else {
        int mm = m0 + r; if (mm > cnt - 1) mm = cnt - 1;
        aRow = (size_t)(abase + mm) * HDIM;
    }
    const __half* aP = (G1 ? g_xh : g_h) + aRow + eoff;
    const __half* bP = (G1 ? g_w1t : g_w2t) +
                       ((size_t)e * NTOT + n0 + r) * KTOT + eoff;

    uint32_t sb = smem_u32(dsm);
    uint32_t dA = sb + 80 * r + 32 * (tid & 1);
    uint32_t dB = dA + 10240;

    // ---- ldmatrix base addresses ----
    int wm = wid & 3, wn = wid >> 2;       // warp tile: rows wm*32, cols wn*64
    uint32_t aOff = sb + 80 * (wm * 32 + (lane & 15)) + 16 * (lane >> 4);
    uint32_t bOff = sb + 10240 +
                    80 * (wn * 64 + (lane & 7) + 8 * (lane >> 4)) +
                    16 * ((lane >> 3) & 1);

    float c[2][8][4];
    #pragma unroll
    for (int i = 0; i < 2; i++)
        #pragma unroll
        for (int j = 0; j < 8; j++)
            #pragma unroll
            for (int q = 0; q < 4; q++) c[i][j][q] = 0.f;

    // ---- prologue: stages 0,1,2 ----
    #pragma unroll
    for (int i = 0; i < 3; i++) {
        uint32_t st = i * STG;
        int k0 = i * 32;
        CPA(dA + st, aP + k0);  CPA(dA + st + 16, aP + k0 + 8);
        CPA(dB + st, bP + k0);  CPA(dB + st + 16, bP + k0 + 8);
        CPC();
    }

    for (int i = 0; i < NC; i++) {
        CPW2();
        __syncthreads();
        if (i + 3 < NC) {
            uint32_t st = ((i + 3) % NSTG) * STG;
            int k0 = (i + 3) * 32;
            CPA(dA + st, aP + k0);  CPA(dA + st + 16, aP + k0 + 8);
            CPA(dB + st, bP + k0);  CPA(dB + st + 16, bP + k0 + 8);
        }
        CPC();

        uint32_t st = (i % NSTG) * STG;
        #pragma unroll
        for (int kk = 0; kk < 2; kk++) {
            uint32_t a0[4], a1[4];
            ldsm4(a0, aOff + st + kk * 32);
            ldsm4(a1, aOff + st + kk * 32 + 1280);
            #pragma unroll
            for (int ng = 0; ng < 4; ng++) {
                uint32_t bf[4];
                ldsm4(bf, bOff + st + ng * 1280 + kk * 32);
                mma16816(c[0][2 * ng],     a0, bf);
                mma16816(c[0][2 * ng + 1], a0, bf + 2);
                mma16816(c[1][2 * ng],     a1, bf);
                mma16816(c[1][2 * ng + 1], a1, bf + 2);
            }
        }
    }

    // ---- epilogue: stage C in smem (pitch 132 floats), then coalesced out ----
    __syncthreads();
    float* sC = (float*)dsm;
    #pragma unroll
    for (int mi = 0; mi < 2; mi++) {
        #pragma unroll
        for (int nf = 0; nf < 8; nf++) {
            int rm = wm * 32 + mi * 16 + (lane >> 2);
            int cn = wn * 64 + nf * 8 + 2 * (lane & 3);
            *(float2*)&sC[rm * 132 + cn]       = make_float2(c[mi][nf][0], c[mi][nf][1]);
            *(float2*)&sC[(rm + 8) * 132 + cn] = make_float2(c[mi][nf][2], c[mi][nf][3]);
        }
    }
    __syncthreads();

    int rr = tid >> 1;
    int cb = (tid & 1) * 64;
    bool mv = (m0 + rr) < cnt;
    if (G1) {
        if (mv) {
            size_t rowb = (size_t)(abase + m0 + rr) * HDIM + n0 + cb;
            #pragma unroll
            for (int g = 0; g < 8; g++) {
                uint32_t H[4];
                #pragma unroll
                for (int p = 0; p < 4; p++) {
                    int col = cb + g * 8 + 2 * p;
                    float v0 = fmaxf(sC[rr * 132 + col]     + s_bias[col],     0.f);
                    float v1 = fmaxf(sC[rr * 132 + col + 1] + s_bias[col + 1], 0.f);
                    H[p] = hpack2(__float2half_rn(v0), __float2half_rn(v1));
                }
                *(uint4*)(g_h + rowb + g * 8) = *(uint4*)H;
            }
        }
    } else {
        if (mv) {
            int enc  = s_tok[rr];
            int tok  = enc >> 1, slot = enc & 1;
            float gt = s_gate[rr];
            __half* dst = g_y + ((size_t)slot * TOKENS + tok) * DDIM + n0 + cb;
            #pragma unroll
            for (int g = 0; g < 8; g++) {
                uint32_t H[4];
                #pragma unroll
                for (int p = 0; p < 4; p++) {
                    int col = cb + g * 8 + 2 * p;
                    float v0 = gt * (sC[rr * 132 + col]     + s_bias[col]);
                    float v1 = gt * (sC[rr * 132 + col + 1] + s_bias[col + 1]);
                    H[p] = hpack2(__float2half_rn(v0), __float2half_rn(v1));
                }
                *(uint4*)(dst + g * 8) = *(uint4*)H;
            }
        }
    }
}

// combine: out = slot0 + slot1 (fp16 partials -> fp32 out), 8 elems/thread
__global__ void combine_kernel(float* __restrict__ out) {
    size_t i = ((size_t)blockIdx.x * 256 + threadIdx.x) * 8;
    uint4 av = *(const uint4*)(g_y + i);
    uint4 bv = *(const uint4*)(g_y + (size_t)TOKENS * DDIM + i);
    const uint32_t* au = (const uint32_t*)&av;
    const uint32_t* bu = (const uint32_t*)&bv;
    float o[8];
    #pragma unroll
    for (int p = 0; p < 4; p++) {
        __half2 ah = *(const __half2*)&au[p];
        __half2 bh = *(const __half2*)&bu[p];
        float2 af = __half22float2(ah);
        float2 bf = __half22float2(bh);
        o[2 * p]     = af.x + bf.x;
        o[2 * p + 1] = af.y + bf.y;
    }
    *(float4*)(out + i)     = *(float4*)(o);
    *(float4*)(out + i + 4) = *(float4*)(o + 4);
}

// ---------------- launch ------------------------------------------------------
extern "C" void kernel_launch(void* const* d_in, const int* in_sizes, int n_in,
                              void* d_out, int out_size) {
    const float* x   = (const float*)d_in[0];
    const float* rw  = (const float*)d_in[1];
    const float* rb  = (const float*)d_in[2];
    const float* w1  = (const float*)d_in[3];
    const float* b1  = (const float*)d_in[4];
    const float* w2  = (const float*)d_in[5];
    const float* b2  = (const float*)d_in[6];
    float*       out = (float*)d_out;

    // handles created once on the first (non-capture) call; capture only
    // records/waits events — a documented capturable multi-stream pattern.
    static cudaStream_t s2 = nullptr;
    static cudaEvent_t evFork = nullptr, evW1 = nullptr, evW2 = nullptr;
    if (!s2) {
        cudaStreamCreateWithFlags(&s2, cudaStreamNonBlocking);
        cudaEventCreateWithFlags(&evFork, cudaEventDisableTiming);
        cudaEventCreateWithFlags(&evW1,   cudaEventDisableTiming);
        cudaEventCreateWithFlags(&evW2,   cudaEventDisableTiming);
    }

    cudaFuncSetAttribute(hgemm_kernel<true>,
                         cudaFuncAttributeMaxDynamicSharedMemorySize, DSMEM);
    cudaFuncSetAttribute(hgemm_kernel<false>,
                         cudaFuncAttributeMaxDynamicSharedMemorySize, DSMEM);

    // fork side stream: weight transposes run concurrent with router / gemm1
    cudaEventRecord(evFork, 0);
    cudaStreamWaitEvent(s2, evFork, 0);
    t_w_kernel<0><<<dim3(HDIM / 32, DDIM / 32, NEXP), dim3(32, 8), 0, s2>>>(w1);
    cudaEventRecord(evW1, s2);
    t_w_kernel<1><<<dim3(DDIM / 32, HDIM / 32, NEXP), dim3(32, 8), 0, s2>>>(w2);
    cudaEventRecord(evW2, s2);

    zero_counts_kernel<<<1, 32>>>();
    router_kernel<<<TOKENS / 8, 256>>>(x, rw, rb);

    cudaStreamWaitEvent(0, evW1, 0);
    hgemm_kernel<true ><<<dim3(HDIM / 128, MTILES), 256, DSMEM>>>(b1);
    cudaStreamWaitEvent(0, evW2, 0);
    hgemm_kernel<false><<<dim3(DDIM / 128, MTILES), 256, DSMEM>>>(b2);
    combine_kernel<<<TOKENS * DDIM / 2048, 256>>>(out);
}

// round 16
// speedup vs baseline: 1.0969x; 1.0553x over previous
#include <cuda_runtime.h>
#include <cuda_fp16.h>
#include <math.h>
#include <stdint.h>

#define TOKENS 65536
#define DDIM   512
#define NEXP   8
#define HDIM   2048
#define CAP    65536
#define MTILES 1032   // ceil((131072 + 8*127)/128)

// ---------------- device scratch (no allocs allowed) -------------------------
__device__ int   g_counts [NEXP];
__device__ int   g_tokens [NEXP * CAP];   // token*2 + slot
__device__ float g_gates  [NEXP * CAP];
__device__ __half g_xh [(size_t)TOKENS * DDIM];          // x fp16 (written by router)
__device__ __half g_w1t[(size_t)NEXP * HDIM * DDIM];     // [E][H][D] K-major
__device__ __half g_w2t[(size_t)NEXP * DDIM * HDIM];     // [E][D][H] K-major
__device__ __half g_h[(size_t)(2 * TOKENS + 1024) * HDIM];  // aligned compact hidden
__device__ __half g_y[(size_t)2 * TOKENS * DDIM];        // slot outputs (fp16)

// ---------------- helpers -----------------------------------------------------
__device__ __forceinline__ uint32_t smem_u32(const void* p) {
    uint32_t a;
    asm("{ .reg .u64 t; cvta.to.shared.u64 t, %1; cvt.u32.u64 %0, t; }" : "=r"(a) : "l"(p));
    return a;
}
__device__ __forceinline__ void ldsm4(uint32_t* r, uint32_t addr) {
    asm volatile("ldmatrix.sync.aligned.m8n8.x4.shared.b16 {%0,%1,%2,%3}, [%4];"
        : "=r"(r[0]), "=r"(r[1]), "=r"(r[2]), "=r"(r[3]) : "r"(addr));
}
__device__ __forceinline__ void mma16816(float* c, const uint32_t* a, const uint32_t* b) {
    asm volatile(
        "mma.sync.aligned.m16n8k16.row.col.f32.f16.f16.f32 "
        "{%0,%1,%2,%3}, {%4,%5,%6,%7}, {%8,%9}, {%0,%1,%2,%3};"
        : "+f"(c[0]), "+f"(c[1]), "+f"(c[2]), "+f"(c[3])
        : "r"(a[0]), "r"(a[1]), "r"(a[2]), "r"(a[3]), "r"(b[0]), "r"(b[1]));
}
#define CPA(dst, src) \
    asm volatile("cp.async.cg.shared.global [%0], [%1], 16;" :: "r"(dst), "l"(src) : "memory")
#define CPC()  asm volatile("cp.async.commit_group;" ::: "memory")
#define CPW2() asm volatile("cp.async.wait_group 2;" ::: "memory")

__device__ __forceinline__ uint32_t hpack2(__half a, __half b) {
    union { __half h[2]; uint32_t u; } t;
    t.h[0] = a; t.h[1] = b;
    return t.u;
}

// ---------------- prep kernels ------------------------------------------------
__global__ void zero_counts_kernel() { if (threadIdx.x < NEXP) g_counts[threadIdx.x] = 0; }

// transpose [R][C] fp32 -> [C][R] fp16 (per expert)
template<int SEL>   // 0: w1 (R=512,C=2048), 1: w2 (R=2048,C=512)
__global__ void t_w_kernel(const float* __restrict__ src) {
    constexpr int R = SEL ? HDIM : DDIM;
    constexpr int C = SEL ? DDIM : HDIM;
    __half* dst = SEL ? g_w2t : g_w1t;
    __shared__ float t[32][33];
    int e = blockIdx.z;
    const float* s = src + (size_t)e * R * C;
    int c0 = blockIdx.x * 32, r0 = blockIdx.y * 32;
    int tx = threadIdx.x, ty = threadIdx.y;
    #pragma unroll
    for (int j = 0; j < 4; j++)
        t[ty + j * 8][tx] = s[(size_t)(r0 + ty + j * 8) * C + c0 + tx];
    __syncthreads();
    #pragma unroll
    for (int j = 0; j < 4; j++) {
        float v = t[tx][ty + j * 8];
        size_t o = ((size_t)e * C + c0 + ty + j * 8) * R + r0 + tx;
        dst[o] = __float2half_rn(v);
    }
}

// ---------------- router (+ fused x -> fp16 conversion), R13 layout -----------
__global__ void router_kernel(const float* __restrict__ x,
                              const float* __restrict__ rw,
                              const float* __restrict__ rb) {
    __shared__ float srw[DDIM * NEXP];
    int tid = threadIdx.x;
    for (int i = tid; i < DDIM * NEXP; i += blockDim.x) srw[i] = rw[i];
    __syncthreads();
    int warp = tid >> 5, lane = tid & 31;
    int t = blockIdx.x * 8 + warp;
    const float* xr = x + (size_t)t * DDIM;

    float acc[NEXP];
    #pragma unroll
    for (int e = 0; e < NEXP; e++) acc[e] = 0.f;
    for (int d = lane; d < DDIM; d += 32) {
        float xv = xr[d];
        #pragma unroll
        for (int e = 0; e < NEXP; e++) acc[e] += xv * srw[d * NEXP + e];
    }
    #pragma unroll
    for (int e = 0; e < NEXP; e++) {
        #pragma unroll
        for (int o = 16; o > 0; o >>= 1)
            acc[e] += __shfl_xor_sync(0xffffffffu, acc[e], o);
    }

    // fused: convert this token's row to fp16 (second pass over x, L1/L2 hot)
    const float4* xr4 = (const float4*)xr;
    #pragma unroll
    for (int it = 0; it < 4; it++) {
        float4 v = xr4[lane + it * 32];
        uint2 H;
        H.x = hpack2(__float2half_rn(v.x), __float2half_rn(v.y));
        H.y = hpack2(__float2half_rn(v.z), __float2half_rn(v.w));
        *(uint2*)(g_xh + (size_t)t * DDIM + (size_t)(lane + it * 32) * 4) = H;
    }

    if (lane == 0) {
        float l[NEXP];
        #pragma unroll
        for (int e = 0; e < NEXP; e++) l[e] = acc[e] + rb[e];
        int e1 = 0;
        #pragma unroll
        for (int e = 1; e < NEXP; e++) if (l[e] > l[e1]) e1 = e;
        int e2 = (e1 == 0) ? 1 : 0;
        #pragma unroll
        for (int e = 0; e < NEXP; e++)
            if (e != e1 && l[e] > l[e2]) e2 = e;
        float d2 = expf(l[e2] - l[e1]);
        float g2 = d2 / (1.f + d2);
        float g1 = 1.f - g2;
        int p1 = atomicAdd(&g_counts[e1], 1);
        g_tokens[e1 * CAP + p1] = t * 2 + 0;  g_gates[e1 * CAP + p1] = g1;
        int p2 = atomicAdd(&g_counts[e2], 1);
        g_tokens[e2 * CAP + p2] = t * 2 + 1;  g_gates[e2 * CAP + p2] = g2;
    }
}

// ---------------- HMMA GEMM (128x128, 256 thr, NSTG=4, 2 CTA/SM) --------------
// M-grid covers the 128-aligned compact row space of ALL experts: zero no-ops.
#define STG   20480
#define NSTG  4
#define DSMEM (NSTG * STG)

template<bool G1>
__global__ void __launch_bounds__(256, 2)
hgemm_kernel(const float* __restrict__ bias_vec) {
    constexpr int KTOT = G1 ? DDIM : HDIM;
    constexpr int NTOT = G1 ? HDIM : DDIM;
    constexpr int NC   = KTOT / 32;

    // ---- locate expert from aligned-compact tile index ----
    int m0g = blockIdx.y * 128;
    int e = -1, abase = 0, cnt = 0;
    #pragma unroll
    for (int k = 0; k < NEXP; k++) {
        if (e < 0) {
            int ck = g_counts[k];
            int ak = (ck + 127) & ~127;
            if (m0g < abase + ak) { e = k; cnt = ck; }
            else abase += ak;
        }
    }
    if (e < 0) return;                  // beyond total aligned rows
    int m0 = m0g - abase;               // local tile start, always < cnt
    int n0 = blockIdx.x * 128;

    extern __shared__ char dsm[];
    __shared__ int   s_tok[128];
    __shared__ float s_gate[128];
    __shared__ float s_bias[128];

    int tid = threadIdx.x;
    int lane = tid & 31, wid = tid >> 5;

    if (tid < 128) {
        int m = m0 + tid; if (m > cnt - 1) m = cnt - 1;
        s_tok[tid]  = g_tokens[e * CAP + m];
        s_gate[tid] = g_gates [e * CAP + m];
        s_bias[tid] = bias_vec[(size_t)e * NTOT + n0 + tid];
    }
    __syncthreads();

    // ---- cp.async mapping: thread t -> row t/2, 32B half (t&1) of 64B row ----
    int r    = tid >> 1;
    int eoff = (tid & 1) * 16;
    size_t aRow;
    if (G1) aRow = (size_t)(s_tok[r] >> 1) * DDIM;
    else {
        int mm = m0 + r; if (mm > cnt - 1) mm = cnt - 1;
        aRow = (size_t)(abase + mm) * HDIM;
    }
    const __half* aP = (G1 ? g_xh : g_h) + aRow + eoff;
    const __half* bP = (G1 ? g_w1t : g_w2t) +
                       ((size_t)e * NTOT + n0 + r) * KTOT + eoff;

    uint32_t sb = smem_u32(dsm);
    uint32_t dA = sb + 80 * r + 32 * (tid & 1);
    uint32_t dB = dA + 10240;

    // ---- ldmatrix base addresses ----
    int wm = wid & 3, wn = wid >> 2;       // warp tile: rows wm*32, cols wn*64
    uint32_t aOff = sb + 80 * (wm * 32 + (lane & 15)) + 16 * (lane >> 4);
    uint32_t bOff = sb + 10240 +
                    80 * (wn * 64 + (lane & 7) + 8 * (lane >> 4)) +
                    16 * ((lane >> 3) & 1);

    float c[2][8][4];
    #pragma unroll
    for (int i = 0; i < 2; i++)
        #pragma unroll
        for (int j = 0; j < 8; j++)
            #pragma unroll
            for (int q = 0; q < 4; q++) c[i][j][q] = 0.f;

    // ---- prologue: stages 0,1,2 ----
    #pragma unroll
    for (int i = 0; i < 3; i++) {
        uint32_t st = i * STG;
        int k0 = i * 32;
        CPA(dA + st, aP + k0);  CPA(dA + st + 16, aP + k0 + 8);
        CPA(dB + st, bP + k0);  CPA(dB + st + 16, bP + k0 + 8);
        CPC();
    }

    for (int i = 0; i < NC; i++) {
        CPW2();
        __syncthreads();
        if (i + 3 < NC) {
            uint32_t st = ((i + 3) % NSTG) * STG;
            int k0 = (i + 3) * 32;
            CPA(dA + st, aP + k0);  CPA(dA + st + 16, aP + k0 + 8);
            CPA(dB + st, bP + k0);  CPA(dB + st + 16, bP + k0 + 8);
        }
        CPC();

        uint32_t st = (i % NSTG) * STG;
        #pragma unroll
        for (int kk = 0; kk < 2; kk++) {
            uint32_t a0[4], a1[4];
            ldsm4(a0, aOff + st + kk * 32);
            ldsm4(a1, aOff + st + kk * 32 + 1280);
            #pragma unroll
            for (int ng = 0; ng < 4; ng++) {
                uint32_t bf[4];
                ldsm4(bf, bOff + st + ng * 1280 + kk * 32);
                mma16816(c[0][2 * ng],     a0, bf);
                mma16816(c[0][2 * ng + 1], a0, bf + 2);
                mma16816(c[1][2 * ng],     a1, bf);
                mma16816(c[1][2 * ng + 1], a1, bf + 2);
            }
        }
    }

    // ---- epilogue: stage C in smem (pitch 132 floats), then coalesced out ----
    __syncthreads();
    float* sC = (float*)dsm;
    #pragma unroll
    for (int mi = 0; mi < 2; mi++) {
        #pragma unroll
        for (int nf = 0; nf < 8; nf++) {
            int rm = wm * 32 + mi * 16 + (lane >> 2);
            int cn = wn * 64 + nf * 8 + 2 * (lane & 3);
            *(float2*)&sC[rm * 132 + cn]       = make_float2(c[mi][nf][0], c[mi][nf][1]);
            *(float2*)&sC[(rm + 8) * 132 + cn] = make_float2(c[mi][nf][2], c[mi][nf][3]);
        }
    }
    __syncthreads();

    int rr = tid >> 1;
    int cb = (tid & 1) * 64;
    bool mv = (m0 + rr) < cnt;
    if (G1) {
        if (mv) {
            size_t rowb = (size_t)(abase + m0 + rr) * HDIM + n0 + cb;
            #pragma unroll
            for (int g = 0; g < 8; g++) {
                uint32_t H[4];
                #pragma unroll
                for (int p = 0; p < 4; p++) {
                    int col = cb + g * 8 + 2 * p;
                    float v0 = fmaxf(sC[rr * 132 + col]     + s_bias[col],     0.f);
                    float v1 = fmaxf(sC[rr * 132 + col + 1] + s_bias[col + 1], 0.f);
                    H[p] = hpack2(__float2half_rn(v0), __float2half_rn(v1));
                }
                *(uint4*)(g_h + rowb + g * 8) = *(uint4*)H;
            }
        }
    } else {
        if (mv) {
            int enc  = s_tok[rr];
            int tok  = enc >> 1, slot = enc & 1;
            float gt = s_gate[rr];
            __half* dst = g_y + ((size_t)slot * TOKENS + tok) * DDIM + n0 + cb;
            #pragma unroll
            for (int g = 0; g < 8; g++) {
                uint32_t H[4];
                #pragma unroll
                for (int p = 0; p < 4; p++) {
                    int col = cb + g * 8 + 2 * p;
                    float v0 = gt * (sC[rr * 132 + col]     + s_bias[col]);
                    float v1 = gt * (sC[rr * 132 + col + 1] + s_bias[col + 1]);
                    H[p] = hpack2(__float2half_rn(v0), __float2half_rn(v1));
                }
                *(uint4*)(dst + g * 8) = *(uint4*)H;
            }
        }
    }
}

// combine: out = slot0 + slot1 (fp16 partials -> fp32 out), 8 elems/thread
__global__ void combine_kernel(float* __restrict__ out) {
    size_t i = ((size_t)blockIdx.x * 256 + threadIdx.x) * 8;
    uint4 av = *(const uint4*)(g_y + i);
    uint4 bv = *(const uint4*)(g_y + (size_t)TOKENS * DDIM + i);
    const uint32_t* au = (const uint32_t*)&av;
    const uint32_t* bu = (const uint32_t*)&bv;
    float o[8];
    #pragma unroll
    for (int p = 0; p < 4; p++) {
        __half2 ah = *(const __half2*)&au[p];
        __half2 bh = *(const __half2*)&bu[p];
        float2 af = __half22float2(ah);
        float2 bf = __half22float2(bh);
        o[2 * p]     = af.x + bf.x;
        o[2 * p + 1] = af.y + bf.y;
    }
    *(float4*)(out + i)     = *(float4*)(o);
    *(float4*)(out + i + 4) = *(float4*)(o + 4);
}

// ---------------- launch ------------------------------------------------------
extern "C" void kernel_launch(void* const* d_in, const int* in_sizes, int n_in,
                              void* d_out, int out_size) {
    const float* x   = (const float*)d_in[0];
    const float* rw  = (const float*)d_in[1];
    const float* rb  = (const float*)d_in[2];
    const float* w1  = (const float*)d_in[3];
    const float* b1  = (const float*)d_in[4];
    const float* w2  = (const float*)d_in[5];
    const float* b2  = (const float*)d_in[6];
    float*       out = (float*)d_out;

    // handles created once on the first (non-capture) call; capture only
    // records/waits events — the documented capturable multi-stream pattern.
    static cudaStream_t s2 = nullptr;
    static cudaEvent_t evFork = nullptr, evW1 = nullptr, evW2 = nullptr;
    if (!s2) {
        cudaStreamCreateWithFlags(&s2, cudaStreamNonBlocking);
        cudaEventCreateWithFlags(&evFork, cudaEventDisableTiming);
        cudaEventCreateWithFlags(&evW1,   cudaEventDisableTiming);
        cudaEventCreateWithFlags(&evW2,   cudaEventDisableTiming);
    }

    cudaFuncSetAttribute(hgemm_kernel<true>,
                         cudaFuncAttributeMaxDynamicSharedMemorySize, DSMEM);
    cudaFuncSetAttribute(hgemm_kernel<false>,
                         cudaFuncAttributeMaxDynamicSharedMemorySize, DSMEM);

    // fork side stream: weight transposes run concurrent with router / gemm1
    cudaEventRecord(evFork, 0);
    cudaStreamWaitEvent(s2, evFork, 0);
    t_w_kernel<0><<<dim3(HDIM / 32, DDIM / 32, NEXP), dim3(32, 8), 0, s2>>>(w1);
    cudaEventRecord(evW1, s2);
    t_w_kernel<1><<<dim3(DDIM / 32, HDIM / 32, NEXP), dim3(32, 8), 0, s2>>>(w2);
    cudaEventRecord(evW2, s2);

    zero_counts_kernel<<<1, 32>>>();
    router_kernel<<<TOKENS / 8, 256>>>(x, rw, rb);

    cudaStreamWaitEvent(0, evW1, 0);
    hgemm_kernel<true ><<<dim3(HDIM / 128, MTILES), 256, DSMEM>>>(b1);
    cudaStreamWaitEvent(0, evW2, 0);
    hgemm_kernel<false><<<dim3(DDIM / 128, MTILES), 256, DSMEM>>>(b2);
    combine_kernel<<<TOKENS * DDIM / 2048, 256>>>(out);
}

// round 17
// speedup vs baseline: 1.0975x; 1.0006x over previous
#include <cuda_runtime.h>
#include <cuda_fp16.h>
#include <math.h>
#include <stdint.h>

#define TOKENS 65536
#define DDIM   512
#define NEXP   8
#define HDIM   2048
#define CAP    65536
#define MTILES 1032   // ceil((131072 + 8*127)/128)

// ---------------- device scratch (no allocs allowed) -------------------------
__device__ int   g_counts [NEXP];
__device__ int   g_tokens [NEXP * CAP];   // token*2 + slot
__device__ float g_gates  [NEXP * CAP];
__device__ __half g_xh [(size_t)TOKENS * DDIM];          // x fp16 (written by router)
__device__ __half g_w1t[(size_t)NEXP * HDIM * DDIM];     // [E][H][D] K-major
__device__ __half g_w2t[(size_t)NEXP * DDIM * HDIM];     // [E][D][H] K-major
__device__ __half g_h[(size_t)(2 * TOKENS + 1024) * HDIM];  // aligned compact hidden
__device__ __half g_y[(size_t)2 * TOKENS * DDIM];        // slot outputs (fp16)

// ---------------- helpers -----------------------------------------------------
__device__ __forceinline__ uint32_t smem_u32(const void* p) {
    uint32_t a;
    asm("{ .reg .u64 t; cvta.to.shared.u64 t, %1; cvt.u32.u64 %0, t; }" : "=r"(a) : "l"(p));
    return a;
}
__device__ __forceinline__ void ldsm4(uint32_t* r, uint32_t addr) {
    asm volatile("ldmatrix.sync.aligned.m8n8.x4.shared.b16 {%0,%1,%2,%3}, [%4];"
        : "=r"(r[0]), "=r"(r[1]), "=r"(r[2]), "=r"(r[3]) : "r"(addr));
}
__device__ __forceinline__ void mma16816(float* c, const uint32_t* a, const uint32_t* b) {
    asm volatile(
        "mma.sync.aligned.m16n8k16.row.col.f32.f16.f16.f32 "
        "{%0,%1,%2,%3}, {%4,%5,%6,%7}, {%8,%9}, {%0,%1,%2,%3};"
        : "+f"(c[0]), "+f"(c[1]), "+f"(c[2]), "+f"(c[3])
        : "r"(a[0]), "r"(a[1]), "r"(a[2]), "r"(a[3]), "r"(b[0]), "r"(b[1]));
}
#define CPA(dst, src) \
    asm volatile("cp.async.cg.shared.global [%0], [%1], 16;" :: "r"(dst), "l"(src) : "memory")
#define CPC()  asm volatile("cp.async.commit_group;" ::: "memory")
#define CPW2() asm volatile("cp.async.wait_group 2;" ::: "memory")

__device__ __forceinline__ uint32_t hpack2(__half a, __half b) {
    union { __half h[2]; uint32_t u; } t;
    t.h[0] = a; t.h[1] = b;
    return t.u;
}

// ---------------- prep kernels ------------------------------------------------
__global__ void zero_counts_kernel() { if (threadIdx.x < NEXP) g_counts[threadIdx.x] = 0; }

// transpose [R][C] fp32 -> [C][R] fp16 (per expert)
template<int SEL>   // 0: w1 (R=512,C=2048), 1: w2 (R=2048,C=512)
__global__ void t_w_kernel(const float* __restrict__ src) {
    constexpr int R = SEL ? HDIM : DDIM;
    constexpr int C = SEL ? DDIM : HDIM;
    __half* dst = SEL ? g_w2t : g_w1t;
    __shared__ float t[32][33];
    int e = blockIdx.z;
    const float* s = src + (size_t)e * R * C;
    int c0 = blockIdx.x * 32, r0 = blockIdx.y * 32;
    int tx = threadIdx.x, ty = threadIdx.y;
    #pragma unroll
    for (int j = 0; j < 4; j++)
        t[ty + j * 8][tx] = s[(size_t)(r0 + ty + j * 8) * C + c0 + tx];
    __syncthreads();
    #pragma unroll
    for (int j = 0; j < 4; j++) {
        float v = t[tx][ty + j * 8];
        size_t o = ((size_t)e * C + c0 + ty + j * 8) * R + r0 + tx;
        dst[o] = __float2half_rn(v);
    }
}

// ---------------- router (+ fused x -> fp16 conversion) -----------------------
// srw staged TRANSPOSED [e][d]: logit-loop bank = d%32 = lane -> conflict-free.
__global__ void router_kernel(const float* __restrict__ x,
                              const float* __restrict__ rw,
                              const float* __restrict__ rb) {
    __shared__ float srw[NEXP * DDIM];           // [e][d], 16 KB
    int tid = threadIdx.x;
    for (int i = tid; i < DDIM * NEXP; i += blockDim.x) {
        int d = i >> 3, e = i & 7;               // rw is [d][e]
        srw[e * DDIM + d] = rw[i];
    }
    __syncthreads();
    int warp = tid >> 5, lane = tid & 31;
    int t = blockIdx.x * 8 + warp;
    const float* xr = x + (size_t)t * DDIM;

    float acc[NEXP];
    #pragma unroll
    for (int e = 0; e < NEXP; e++) acc[e] = 0.f;
    for (int d = lane; d < DDIM; d += 32) {
        float xv = xr[d];
        #pragma unroll
        for (int e = 0; e < NEXP; e++) acc[e] += xv * srw[e * DDIM + d];
    }
    #pragma unroll
    for (int e = 0; e < NEXP; e++) {
        #pragma unroll
        for (int o = 16; o > 0; o >>= 1)
            acc[e] += __shfl_xor_sync(0xffffffffu, acc[e], o);
    }

    // fused: convert this token's row to fp16 (second pass over x, L1/L2 hot)
    const float4* xr4 = (const float4*)xr;
    #pragma unroll
    for (int it = 0; it < 4; it++) {
        float4 v = xr4[lane + it * 32];
        uint2 H;
        H.x = hpack2(__float2half_rn(v.x), __float2half_rn(v.y));
        H.y = hpack2(__float2half_rn(v.z), __float2half_rn(v.w));
        *(uint2*)(g_xh + (size_t)t * DDIM + (size_t)(lane + it * 32) * 4) = H;
    }

    if (lane == 0) {
        float l[NEXP];
        #pragma unroll
        for (int e = 0; e < NEXP; e++) l[e] = acc[e] + rb[e];
        int e1 = 0;
        #pragma unroll
        for (int e = 1; e < NEXP; e++) if (l[e] > l[e1]) e1 = e;
        int e2 = (e1 == 0) ? 1 : 0;
        #pragma unroll
        for (int e = 0; e < NEXP; e++)
            if (e != e1 && l[e] > l[e2]) e2 = e;
        float d2 = expf(l[e2] - l[e1]);
        float g2 = d2 / (1.f + d2);
        float g1 = 1.f - g2;
        int p1 = atomicAdd(&g_counts[e1], 1);
        g_tokens[e1 * CAP + p1] = t * 2 + 0;  g_gates[e1 * CAP + p1] = g1;
        int p2 = atomicAdd(&g_counts[e2], 1);
        g_tokens[e2 * CAP + p2] = t * 2 + 1;  g_gates[e2 * CAP + p2] = g2;
    }
}

// ---------------- HMMA GEMM (128x128, 256 thr, NSTG=4, 2 CTA/SM) --------------
// M-grid covers the 128-aligned compact row space of ALL experts: zero no-ops.
#define STG   20480
#define NSTG  4
#define DSMEM (NSTG * STG)

template<bool G1>
__global__ void __launch_bounds__(256, 2)
hgemm_kernel(const float* __restrict__ bias_vec) {
    constexpr int KTOT = G1 ? DDIM : HDIM;
    constexpr int NTOT = G1 ? HDIM : DDIM;
    constexpr int NC   = KTOT / 32;

    // ---- locate expert from aligned-compact tile index ----
    int m0g = blockIdx.y * 128;
    int e = -1, abase = 0, cnt = 0;
    #pragma unroll
    for (int k = 0; k < NEXP; k++) {
        if (e < 0) {
            int ck = g_counts[k];
            int ak = (ck + 127) & ~127;
            if (m0g < abase + ak) { e = k; cnt = ck; }
            else abase += ak;
        }
    }
    if (e < 0) return;                  // beyond total aligned rows
    int m0 = m0g - abase;               // local tile start, always < cnt
    int n0 = blockIdx.x * 128;

    extern __shared__ char dsm[];
    __shared__ int   s_tok[128];
    __shared__ float s_gate[128];
    __shared__ float s_bias[128];

    int tid = threadIdx.x;
    int lane = tid & 31, wid = tid >> 5;

    if (tid < 128) {
        int m = m0 + tid; if (m > cnt - 1) m = cnt - 1;
        s_tok[tid]  = g_tokens[e * CAP + m];
        s_gate[tid] = g_gates [e * CAP + m];
        s_bias[tid] = bias_vec[(size_t)e * NTOT + n0 + tid];
    }
    __syncthreads();

    // ---- cp.async mapping: thread t -> row t/2, 32B half (t&1) of 64B row ----
    int r    = tid >> 1;
    int eoff = (tid & 1) * 16;
    size_t aRow;
    if (G1) aRow = (size_t)(s_tok[r] >> 1) * DDIM;
    else {
        int mm = m0 + r; if (mm > cnt - 1) mm = cnt - 1;
        aRow = (size_t)(abase + mm) * HDIM;
    }
    const __half* aP = (G1 ? g_xh : g_h) + aRow + eoff;
    const __half* bP = (G1 ? g_w1t : g_w2t) +
                       ((size_t)e * NTOT + n0 + r) * KTOT + eoff;

    uint32_t sb = smem_u32(dsm);
    uint32_t dA = sb + 80 * r + 32 * (tid & 1);
    uint32_t dB = dA + 10240;

    // ---- ldmatrix base addresses ----
    int wm = wid & 3, wn = wid >> 2;       // warp tile: rows wm*32, cols wn*64
    uint32_t aOff = sb + 80 * (wm * 32 + (lane & 15)) + 16 * (lane >> 4);
    uint32_t bOff = sb + 10240 +
                    80 * (wn * 64 + (lane & 7) + 8 * (lane >> 4)) +
                    16 * ((lane >> 3) & 1);

    float c[2][8][4];
    #pragma unroll
    for (int i = 0; i < 2; i++)
        #pragma unroll
        for (int j = 0; j < 8; j++)
            #pragma unroll
            for (int q = 0; q < 4; q++) c[i][j][q] = 0.f;

    // ---- prologue: stages 0,1,2 ----
    #pragma unroll
    for (int i = 0; i < 3; i++) {
        uint32_t st = i * STG;
        int k0 = i * 32;
        CPA(dA + st, aP + k0);  CPA(dA + st + 16, aP + k0 + 8);
        CPA(dB + st, bP + k0);  CPA(dB + st + 16, bP + k0 + 8);
        CPC();
    }

    for (int i = 0; i < NC; i++) {
        CPW2();
        __syncthreads();
        if (i + 3 < NC) {
            uint32_t st = ((i + 3) % NSTG) * STG;
            int k0 = (i + 3) * 32;
            CPA(dA + st, aP + k0);  CPA(dA + st + 16, aP + k0 + 8);
            CPA(dB + st, bP + k0);  CPA(dB + st + 16, bP + k0 + 8);
        }
        CPC();

        uint32_t st = (i % NSTG) * STG;
        #pragma unroll
        for (int kk = 0; kk < 2; kk++) {
            uint32_t a0[4], a1[4];
            ldsm4(a0, aOff + st + kk * 32);
            ldsm4(a1, aOff + st + kk * 32 + 1280);
            #pragma unroll
            for (int ng = 0; ng < 4; ng++) {
                uint32_t bf[4];
                ldsm4(bf, bOff + st + ng * 1280 + kk * 32);
                mma16816(c[0][2 * ng],     a0, bf);
                mma16816(c[0][2 * ng + 1], a0, bf + 2);
                mma16816(c[1][2 * ng],     a1, bf);
                mma16816(c[1][2 * ng + 1], a1, bf + 2);
            }
        }
    }

    // ---- epilogue: stage C in smem (pitch 132 floats), then coalesced out ----
    __syncthreads();
    float* sC = (float*)dsm;
    #pragma unroll
    for (int mi = 0; mi < 2; mi++) {
        #pragma unroll
        for (int nf = 0; nf < 8; nf++) {
            int rm = wm * 32 + mi * 16 + (lane >> 2);
            int cn = wn * 64 + nf * 8 + 2 * (lane & 3);
            *(float2*)&sC[rm * 132 + cn]       = make_float2(c[mi][nf][0], c[mi][nf][1]);
            *(float2*)&sC[(rm + 8) * 132 + cn] = make_float2(c[mi][nf][2], c[mi][nf][3]);
        }
    }
    __syncthreads();

    int rr = tid >> 1;
    int cb = (tid & 1) * 64;
    bool mv = (m0 + rr) < cnt;
    if (G1) {
        if (mv) {
            size_t rowb = (size_t)(abase + m0 + rr) * HDIM + n0 + cb;
            #pragma unroll
            for (int g = 0; g < 8; g++) {
                uint32_t H[4];
                #pragma unroll
                for (int p = 0; p < 4; p++) {
                    int col = cb + g * 8 + 2 * p;
                    float v0 = fmaxf(sC[rr * 132 + col]     + s_bias[col],     0.f);
                    float v1 = fmaxf(sC[rr * 132 + col + 1] + s_bias[col + 1], 0.f);
                    H[p] = hpack2(__float2half_rn(v0), __float2half_rn(v1));
                }
                *(uint4*)(g_h + rowb + g * 8) = *(uint4*)H;
            }
        }
    } else {
        if (mv) {
            int enc  = s_tok[rr];
            int tok  = enc >> 1, slot = enc & 1;
            float gt = s_gate[rr];
            __half* dst = g_y + ((size_t)slot * TOKENS + tok) * DDIM + n0 + cb;
            #pragma unroll
            for (int g = 0; g < 8; g++) {
                uint32_t H[4];
                #pragma unroll
                for (int p = 0; p < 4; p++) {
                    int col = cb + g * 8 + 2 * p;
                    float v0 = gt * (sC[rr * 132 + col]     + s_bias[col]);
                    float v1 = gt * (sC[rr * 132 + col + 1] + s_bias[col + 1]);
                    H[p] = hpack2(__float2half_rn(v0), __float2half_rn(v1));
                }
                *(uint4*)(dst + g * 8) = *(uint4*)H;
            }
        }
    }
}

// combine: out = slot0 + slot1 (fp16 partials -> fp32 out), 8 elems/thread
__global__ void combine_kernel(float* __restrict__ out) {
    size_t i = ((size_t)blockIdx.x * 256 + threadIdx.x) * 8;
    uint4 av = *(const uint4*)(g_y + i);
    uint4 bv = *(const uint4*)(g_y + (size_t)TOKENS * DDIM + i);
    const uint32_t* au = (const uint32_t*)&av;
    const uint32_t* bu = (const uint32_t*)&bv;
    float o[8];
    #pragma unroll
    for (int p = 0; p < 4; p++) {
        __half2 ah = *(const __half2*)&au[p];
        __half2 bh = *(const __half2*)&bu[p];
        float2 af = __half22float2(ah);
        float2 bf = __half22float2(bh);
        o[2 * p]     = af.x + bf.x;
        o[2 * p + 1] = af.y + bf.y;
    }
    *(float4*)(out + i)     = *(float4*)(o);
    *(float4*)(out + i + 4) = *(float4*)(o + 4);
}

// ---------------- launch ------------------------------------------------------
extern "C" void kernel_launch(void* const* d_in, const int* in_sizes, int n_in,
                              void* d_out, int out_size) {
    const float* x   = (const float*)d_in[0];
    const float* rw  = (const float*)d_in[1];
    const float* rb  = (const float*)d_in[2];
    const float* w1  = (const float*)d_in[3];
    const float* b1  = (const float*)d_in[4];
    const float* w2  = (const float*)d_in[5];
    const float* b2  = (const float*)d_in[6];
    float*       out = (float*)d_out;

    // handles created once on the first (non-capture) call; capture only
    // records/waits events — the documented capturable multi-stream pattern.
    static cudaStream_t s2 = nullptr;
    static cudaEvent_t evFork = nullptr, evW1 = nullptr, evW2 = nullptr;
    if (!s2) {
        cudaStreamCreateWithFlags(&s2, cudaStreamNonBlocking);
        cudaEventCreateWithFlags(&evFork, cudaEventDisableTiming);
        cudaEventCreateWithFlags(&evW1,   cudaEventDisableTiming);
        cudaEventCreateWithFlags(&evW2,   cudaEventDisableTiming);
    }

    cudaFuncSetAttribute(hgemm_kernel<true>,
                         cudaFuncAttributeMaxDynamicSharedMemorySize, DSMEM);
    cudaFuncSetAttribute(hgemm_kernel<false>,
                         cudaFuncAttributeMaxDynamicSharedMemorySize, DSMEM);

    // fork side stream: weight transposes run concurrent with router / gemm1
    cudaEventRecord(evFork, 0);
    cudaStreamWaitEvent(s2, evFork, 0);
    t_w_kernel<0><<<dim3(HDIM / 32, DDIM / 32, NEXP), dim3(32, 8), 0, s2>>>(w1);
    cudaEventRecord(evW1, s2);
    t_w_kernel<1><<<dim3(DDIM / 32, HDIM / 32, NEXP), dim3(32, 8), 0, s2>>>(w2);
    cudaEventRecord(evW2, s2);

    zero_counts_kernel<<<1, 32>>>();
    router_kernel<<<TOKENS / 8, 256>>>(x, rw, rb);

    cudaStreamWaitEvent(0, evW1, 0);
    hgemm_kernel<true ><<<dim3(HDIM / 128, MTILES), 256, DSMEM>>>(b1);
    cudaStreamWaitEvent(0, evW2, 0);
    hgemm_kernel<false><<<dim3(DDIM / 128, MTILES), 256, DSMEM>>>(b2);
    combine_kernel<<<TOKENS * DDIM / 2048, 256>>>(out);
}